// round 9
// baseline (speedup 1.0000x reference)
#include <cuda_runtime.h>

// NCC loss, 9x9 box, zero pad, win_size=81.
// predict/target: [32,1,512,512] f32 -> scalar f32 = 1 - mean(cross^2/(Ivar*Jvar+1e-6))
//
// One block = one (batch, 64-row strip), full 512-col width via f32x2 packing of
// column halves (x, x+256). 256 blocks, 256 threads, __launch_bounds__(256,2)
// -> 2 blocks/SM (16 warps), single wave on 148 SMs.

typedef unsigned long long u64;

__device__ __forceinline__ u64 pk2(float lo, float hi) {
    u64 r; asm("mov.b64 %0,{%1,%2};" : "=l"(r) : "f"(lo), "f"(hi)); return r;
}
__device__ __forceinline__ void upk2(u64 v, float& lo, float& hi) {
    asm("mov.b64 {%0,%1},%2;" : "=f"(lo), "=f"(hi) : "l"(v));
}
__device__ __forceinline__ u64 add2(u64 a, u64 b) {
    u64 d; asm("add.rn.f32x2 %0,%1,%2;" : "=l"(d) : "l"(a), "l"(b)); return d;
}
__device__ __forceinline__ u64 mul2(u64 a, u64 b) {
    u64 d; asm("mul.rn.f32x2 %0,%1,%2;" : "=l"(d) : "l"(a), "l"(b)); return d;
}
__device__ __forceinline__ u64 fma2(u64 a, u64 b, u64 c) {
    u64 d; asm("fma.rn.f32x2 %0,%1,%2,%3;" : "=l"(d) : "l"(a), "l"(b), "l"(c)); return d;
}

constexpr int W      = 512;
constexpr int H      = 512;
constexpr int HW     = W * H;
constexpr int BATCH  = 32;
constexpr int ROWS   = 64;                 // output rows per block
constexpr int STRIPS = H / ROWS;           // 8
constexpr int NBLK   = BATCH * STRIPS;     // 256
constexpr int TPB    = 256;                // thread x -> output cols x and x+256
constexpr float INV81 = 1.0f / 81.0f;

__device__ float g_partials[NBLK];
__device__ unsigned int g_ticket = 0;

__global__ void __launch_bounds__(TPB, 2)
ncc_main_kernel(const float* __restrict__ gI, const float* __restrict__ gJ,
                float* __restrict__ out) {
    // packed row entries: {Ipair(col p, col p+256), Jpair}; p in [-4,260) -> slot p+4
    __shared__ ulonglong2 srow[2][264];
    __shared__ u64 s_ringIJ[9][TPB];       // IJ ring lives in smem to save 18 regs
    __shared__ float s_wsum[TPB / 32];
    __shared__ int s_last;

    const int x     = threadIdx.x;         // 0..255
    const int bx    = blockIdx.x;
    const int strip = bx & 7;
    const int batch = bx >> 3;
    const int y0    = strip * ROWS;

    const float* pI = gI + (size_t)batch * HW;
    const float* pJ = gJ + (size_t)batch * HW;

    const u64 ZERO = 0ull;
    const u64 NEG1 = pk2(-1.0f, -1.0f);
    const u64 M81  = pk2(-INV81, -INV81);
    const u64 EPS  = pk2(1e-6f, 1e-6f);

    // 9-deep packed register rings for 4 quantities (IJ ring is in smem)
    u64 rI[9], rJ[9], rI2[9], rJ2[9];
#pragma unroll
    for (int k = 0; k < 9; ++k) {
        rI[k] = ZERO; rJ[k] = ZERO; rI2[k] = ZERO; rJ2[k] = ZERO;
        s_ringIJ[k][x] = ZERO;
    }
    u64 VI = ZERO, VJ = ZERO, VI2 = ZERO, VJ2 = ZERO, VIJ = ZERO;
    float acc = 0.0f;

#pragma unroll 1
    for (int m = 0; m < 8; ++m) {
#pragma unroll
        for (int k = 0; k < 9; ++k) {
            const int it = m * 9 + k;
            const int r  = y0 - 4 + it;
            const bool inRow = (unsigned)r < (unsigned)H;
            const int buf = it & 1;
            const int rb  = r * W;

            // main entry: cols (x, x+256) of both images — fully in range
            {
                float iA = 0.f, iB = 0.f, jA = 0.f, jB = 0.f;
                if (inRow) {
                    iA = pI[rb + x]; iB = pI[rb + x + 256];
                    jA = pJ[rb + x]; jB = pJ[rb + x + 256];
                }
                ulonglong2 e; e.x = pk2(iA, iB); e.y = pk2(jA, jB);
                srow[buf][4 + x] = e;
            }
            // halo entries: p in [-4,0) (lo out-of-image, hi = col p+256 valid)
            //               p in [256,260) (lo = col p valid, hi out-of-image)
            if (x < 8) {
                const bool left = (x < 4);
                const int slot  = left ? x : (256 + x);          // p+4
                const int col   = left ? (x + 252) : (x + 252);  // valid col: p+256 | p
                float iv = 0.f, jv = 0.f;
                if (inRow) { iv = pI[rb + col]; jv = pJ[rb + col]; }
                ulonglong2 e;
                e.x = left ? pk2(0.f, iv) : pk2(iv, 0.f);
                e.y = left ? pk2(0.f, jv) : pk2(jv, 0.f);
                srow[buf][slot] = e;
            }
            __syncthreads();

            // gather 9 taps (independent LDS.128s), then tree/dual-chain reduce
            u64 A[9], C[9];
#pragma unroll
            for (int t = 0; t < 9; ++t) {
                const ulonglong2 e = srow[buf][x + t];
                A[t] = e.x; C[t] = e.y;
            }
            // plain sums: balanced tree (depth 4)
            u64 hI = add2(add2(add2(A[0], A[1]), add2(A[2], A[3])),
                          add2(add2(A[4], A[5]), add2(A[6], A[7])));
            hI = add2(hI, A[8]);
            u64 hJ = add2(add2(add2(C[0], C[1]), add2(C[2], C[3])),
                          add2(add2(C[4], C[5]), add2(C[6], C[7])));
            hJ = add2(hJ, C[8]);
            // product sums: two interleaved fma chains each (depth ~5)
            u64 e0, o0;
            e0 = mul2(A[0], A[0]); e0 = fma2(A[2], A[2], e0); e0 = fma2(A[4], A[4], e0);
            e0 = fma2(A[6], A[6], e0); e0 = fma2(A[8], A[8], e0);
            o0 = mul2(A[1], A[1]); o0 = fma2(A[3], A[3], o0); o0 = fma2(A[5], A[5], o0);
            o0 = fma2(A[7], A[7], o0);
            u64 hI2 = add2(e0, o0);
            e0 = mul2(C[0], C[0]); e0 = fma2(C[2], C[2], e0); e0 = fma2(C[4], C[4], e0);
            e0 = fma2(C[6], C[6], e0); e0 = fma2(C[8], C[8], e0);
            o0 = mul2(C[1], C[1]); o0 = fma2(C[3], C[3], o0); o0 = fma2(C[5], C[5], o0);
            o0 = fma2(C[7], C[7], o0);
            u64 hJ2 = add2(e0, o0);
            e0 = mul2(A[0], C[0]); e0 = fma2(A[2], C[2], e0); e0 = fma2(A[4], C[4], e0);
            e0 = fma2(A[6], C[6], e0); e0 = fma2(A[8], C[8], e0);
            o0 = mul2(A[1], C[1]); o0 = fma2(A[3], C[3], o0); o0 = fma2(A[5], C[5], o0);
            o0 = fma2(A[7], C[7], o0);
            u64 hIJ = add2(e0, o0);

            // vertical running 9-window: V += h_new - h_old
            VI  = add2(VI,  hI );  VI  = fma2(rI [k], NEG1, VI );  rI [k] = hI;
            VJ  = add2(VJ,  hJ );  VJ  = fma2(rJ [k], NEG1, VJ );  rJ [k] = hJ;
            VI2 = add2(VI2, hI2);  VI2 = fma2(rI2[k], NEG1, VI2);  rI2[k] = hI2;
            VJ2 = add2(VJ2, hJ2);  VJ2 = fma2(rJ2[k], NEG1, VJ2);  rJ2[k] = hJ2;
            {
                const u64 oldIJ = s_ringIJ[k][x];
                VIJ = add2(VIJ, hIJ);  VIJ = fma2(oldIJ, NEG1, VIJ);
                s_ringIJ[k][x] = hIJ;   // thread-private slot, no barrier needed
            }

            if (it >= 8) {
                const u64 tIn   = mul2(VI, M81);        // -VI/81
                const u64 tJn   = mul2(VJ, M81);        // -VJ/81
                const u64 cross = fma2(tIn, VJ, VIJ);   // IJ - VI*VJ/81
                const u64 Ivar  = fma2(tIn, VI, VI2);
                const u64 Jvar  = fma2(tJn, VJ, VJ2);
                const u64 num   = mul2(cross, cross);
                const u64 den   = fma2(Ivar, Jvar, EPS);
                float n0, n1, d0, d1;
                upk2(num, n0, n1);
                upk2(den, d0, d1);
                acc += __fdividef(n0, d0);
                acc += __fdividef(n1, d1);
            }
        }
    }

    // deterministic block reduction (8 warps)
#pragma unroll
    for (int o = 16; o > 0; o >>= 1) acc += __shfl_xor_sync(0xffffffffu, acc, o);
    if ((x & 31) == 0) s_wsum[x >> 5] = acc;
    __syncthreads();
    if (x == 0) {
        float v = 0.f;
#pragma unroll
        for (int w = 0; w < TPB / 32; ++w) v += s_wsum[w];
        g_partials[bx] = v;
        __threadfence();
        unsigned t = atomicAdd(&g_ticket, 1u);
        s_last = (t == (unsigned)(NBLK - 1)) ? 1 : 0;
    }
    __syncthreads();

    // last block performs the fixed-order final sum (deterministic)
    if (s_last) {
        const volatile float* gp = g_partials;
        float v = gp[x];                        // 256 threads, 256 partials
#pragma unroll
        for (int o = 16; o > 0; o >>= 1) v += __shfl_xor_sync(0xffffffffu, v, o);
        if ((x & 31) == 0) s_wsum[x >> 5] = v;
        __syncthreads();
        if (x == 0) {
            float s = 0.f;
#pragma unroll
            for (int w = 0; w < TPB / 32; ++w) s += s_wsum[w];
            out[0] = 1.0f - s * (1.0f / 8388608.0f);   // N = 2^23 exact
            g_ticket = 0;                               // reset for next graph replay
        }
    }
}

extern "C" void kernel_launch(void* const* d_in, const int* in_sizes, int n_in,
                              void* d_out, int out_size) {
    const float* predict = (const float*)d_in[0];
    const float* target  = (const float*)d_in[1];
    ncc_main_kernel<<<NBLK, TPB>>>(predict, target, (float*)d_out);
}

// round 10
// speedup vs baseline: 1.0323x; 1.0323x over previous
#include <cuda_runtime.h>

// NCC loss, 9x9 box, zero pad, win_size=81.
// predict/target: [32,1,512,512] f32 -> scalar f32 = 1 - mean(cross^2/(Ivar*Jvar+1e-6))
//
// f32x2-packed column halves (cols x, x+256). One block = (batch, 57-row strip).
// 288 blocks x 256 threads, 2 blocks/SM -> single wave on 144 SMs.
// Software-pipelined row prefetch hides the (L2-hot) global load latency.

typedef unsigned long long u64;

__device__ __forceinline__ u64 pk2(float lo, float hi) {
    u64 r; asm("mov.b64 %0,{%1,%2};" : "=l"(r) : "f"(lo), "f"(hi)); return r;
}
__device__ __forceinline__ void upk2(u64 v, float& lo, float& hi) {
    asm("mov.b64 {%0,%1},%2;" : "=f"(lo), "=f"(hi) : "l"(v));
}
__device__ __forceinline__ u64 add2(u64 a, u64 b) {
    u64 d; asm("add.rn.f32x2 %0,%1,%2;" : "=l"(d) : "l"(a), "l"(b)); return d;
}
__device__ __forceinline__ u64 mul2(u64 a, u64 b) {
    u64 d; asm("mul.rn.f32x2 %0,%1,%2;" : "=l"(d) : "l"(a), "l"(b)); return d;
}
__device__ __forceinline__ u64 fma2(u64 a, u64 b, u64 c) {
    u64 d; asm("fma.rn.f32x2 %0,%1,%2,%3;" : "=l"(d) : "l"(a), "l"(b), "l"(c)); return d;
}

constexpr int W      = 512;
constexpr int H      = 512;
constexpr int HW     = W * H;
constexpr int BATCH  = 32;
constexpr int STRIPS = 9;
constexpr int SROWS  = 57;                  // strips 0..7: 57 rows, strip 8: 56 (masked)
constexpr int NBLK   = BATCH * STRIPS;      // 288
constexpr int TPB    = 256;
constexpr int ITERS  = SROWS + 8;           // 65
constexpr float INV81 = 1.0f / 81.0f;

__device__ float g_partials[NBLK];
__device__ unsigned int g_ticket = 0;

// prefetched row (packed main entry + halo scalar for threads x<8)
struct RowPf { u64 mI, mJ; float hI, hJ; };

__device__ __forceinline__ RowPf load_row(const float* __restrict__ pI,
                                          const float* __restrict__ pJ,
                                          int r, int x) {
    RowPf p; p.mI = 0ull; p.mJ = 0ull; p.hI = 0.f; p.hJ = 0.f;
    if ((unsigned)r < (unsigned)H) {
        const float* ri = pI + r * W;
        const float* rj = pJ + r * W;
        p.mI = pk2(ri[x], ri[x + 256]);
        p.mJ = pk2(rj[x], rj[x + 256]);
        if (x < 8) { p.hI = ri[x + 252]; p.hJ = rj[x + 252]; }
    }
    return p;
}

__global__ void __launch_bounds__(TPB, 2)
ncc_main_kernel(const float* __restrict__ gI, const float* __restrict__ gJ,
                float* __restrict__ out) {
    __shared__ ulonglong2 srow[2][264];     // packed {Ipair, Jpair}, slot = col+4
    __shared__ u64 s_ringIJ[9][TPB];        // IJ vertical ring in smem (reg relief)
    __shared__ float s_wsum[TPB / 32];
    __shared__ int s_last;

    const int x     = threadIdx.x;          // 0..255
    const int bx    = blockIdx.x;
    const int strip = bx % STRIPS;
    const int batch = bx / STRIPS;
    const int y0    = strip * SROWS;

    const float* pI = gI + (size_t)batch * HW;
    const float* pJ = gJ + (size_t)batch * HW;

    const u64 ZERO = 0ull;
    const u64 NEG1 = pk2(-1.0f, -1.0f);
    const u64 M81  = pk2(-INV81, -INV81);
    const u64 EPS  = pk2(1e-6f, 1e-6f);

    u64 rI[9], rJ[9], rI2[9], rJ2[9];
#pragma unroll
    for (int k = 0; k < 9; ++k) {
        rI[k] = ZERO; rJ[k] = ZERO; rI2[k] = ZERO; rJ2[k] = ZERO;
        s_ringIJ[k][x] = ZERO;
    }
    u64 VI = ZERO, VJ = ZERO, VI2 = ZERO, VJ2 = ZERO, VIJ = ZERO;
    float acc = 0.0f;

    RowPf pf = load_row(pI, pJ, y0 - 4, x);   // prologue prefetch

#pragma unroll 1
    for (int m = 0; m < 8; ++m) {
#pragma unroll
        for (int k = 0; k < 9; ++k) {
            const int it = m * 9 + k;
            if (it >= ITERS) goto reduce;               // uniform exit
            const int buf = it & 1;

            // publish prefetched row
            {
                ulonglong2 e; e.x = pf.mI; e.y = pf.mJ;
                srow[buf][4 + x] = e;
                if (x < 8) {
                    const bool left = (x < 4);
                    ulonglong2 h;
                    h.x = left ? pk2(0.f, pf.hI) : pk2(pf.hI, 0.f);
                    h.y = left ? pk2(0.f, pf.hJ) : pk2(pf.hJ, 0.f);
                    srow[buf][left ? x : (256 + x)] = h;
                }
            }
            __syncthreads();

            // prefetch next row (latency covered by the compute below)
            pf = load_row(pI, pJ, y0 - 3 + it, x);

            // gather 9 taps, tree/dual-chain reduce (packed over the 2 halves)
            u64 A[9], C[9];
#pragma unroll
            for (int t = 0; t < 9; ++t) {
                const ulonglong2 e = srow[buf][x + t];
                A[t] = e.x; C[t] = e.y;
            }
            u64 hI = add2(add2(add2(A[0], A[1]), add2(A[2], A[3])),
                          add2(add2(A[4], A[5]), add2(A[6], A[7])));
            hI = add2(hI, A[8]);
            u64 hJ = add2(add2(add2(C[0], C[1]), add2(C[2], C[3])),
                          add2(add2(C[4], C[5]), add2(C[6], C[7])));
            hJ = add2(hJ, C[8]);
            u64 e0, o0;
            e0 = mul2(A[0], A[0]); e0 = fma2(A[2], A[2], e0); e0 = fma2(A[4], A[4], e0);
            e0 = fma2(A[6], A[6], e0); e0 = fma2(A[8], A[8], e0);
            o0 = mul2(A[1], A[1]); o0 = fma2(A[3], A[3], o0); o0 = fma2(A[5], A[5], o0);
            o0 = fma2(A[7], A[7], o0);
            const u64 hI2 = add2(e0, o0);
            e0 = mul2(C[0], C[0]); e0 = fma2(C[2], C[2], e0); e0 = fma2(C[4], C[4], e0);
            e0 = fma2(C[6], C[6], e0); e0 = fma2(C[8], C[8], e0);
            o0 = mul2(C[1], C[1]); o0 = fma2(C[3], C[3], o0); o0 = fma2(C[5], C[5], o0);
            o0 = fma2(C[7], C[7], o0);
            const u64 hJ2 = add2(e0, o0);
            e0 = mul2(A[0], C[0]); e0 = fma2(A[2], C[2], e0); e0 = fma2(A[4], C[4], e0);
            e0 = fma2(A[6], C[6], e0); e0 = fma2(A[8], C[8], e0);
            o0 = mul2(A[1], C[1]); o0 = fma2(A[3], C[3], o0); o0 = fma2(A[5], C[5], o0);
            o0 = fma2(A[7], C[7], o0);
            const u64 hIJ = add2(e0, o0);

            // vertical running 9-window
            VI  = add2(VI,  hI );  VI  = fma2(rI [k], NEG1, VI );  rI [k] = hI;
            VJ  = add2(VJ,  hJ );  VJ  = fma2(rJ [k], NEG1, VJ );  rJ [k] = hJ;
            VI2 = add2(VI2, hI2);  VI2 = fma2(rI2[k], NEG1, VI2);  rI2[k] = hI2;
            VJ2 = add2(VJ2, hJ2);  VJ2 = fma2(rJ2[k], NEG1, VJ2);  rJ2[k] = hJ2;
            {
                const u64 oldIJ = s_ringIJ[k][x];
                VIJ = add2(VIJ, hIJ);  VIJ = fma2(oldIJ, NEG1, VIJ);
                s_ringIJ[k][x] = hIJ;   // thread-private slot, no barrier needed
            }

            if (it >= 8 && (y0 + it - 8) < H) {    // orow guard (strip 8 tail masked)
                const u64 tIn   = mul2(VI, M81);
                const u64 tJn   = mul2(VJ, M81);
                const u64 cross = fma2(tIn, VJ, VIJ);
                const u64 Ivar  = fma2(tIn, VI, VI2);
                const u64 Jvar  = fma2(tJn, VJ, VJ2);
                const u64 num   = mul2(cross, cross);
                const u64 den   = fma2(Ivar, Jvar, EPS);
                float n0, n1, d0, d1;
                upk2(num, n0, n1);
                upk2(den, d0, d1);
                acc += __fdividef(n0, d0);
                acc += __fdividef(n1, d1);
            }
        }
    }
reduce:
    // deterministic block reduction (8 warps)
#pragma unroll
    for (int o = 16; o > 0; o >>= 1) acc += __shfl_xor_sync(0xffffffffu, acc, o);
    if ((x & 31) == 0) s_wsum[x >> 5] = acc;
    __syncthreads();
    if (x == 0) {
        float v = 0.f;
#pragma unroll
        for (int w = 0; w < TPB / 32; ++w) v += s_wsum[w];
        g_partials[bx] = v;
        __threadfence();
        unsigned t = atomicAdd(&g_ticket, 1u);
        s_last = (t == (unsigned)(NBLK - 1)) ? 1 : 0;
    }
    __syncthreads();

    // last block: fixed-order final sum (deterministic)
    if (s_last) {
        const volatile float* gp = g_partials;
        float v = gp[x];
        if (x < NBLK - 256) v += gp[256 + x];     // 288 partials over 256 threads
#pragma unroll
        for (int o = 16; o > 0; o >>= 1) v += __shfl_xor_sync(0xffffffffu, v, o);
        if ((x & 31) == 0) s_wsum[x >> 5] = v;
        __syncthreads();
        if (x == 0) {
            float s = 0.f;
#pragma unroll
            for (int w = 0; w < TPB / 32; ++w) s += s_wsum[w];
            out[0] = 1.0f - s * (1.0f / 8388608.0f);   // N = 2^23 exact
            g_ticket = 0;                               // reset for next graph replay
        }
    }
}

extern "C" void kernel_launch(void* const* d_in, const int* in_sizes, int n_in,
                              void* d_out, int out_size) {
    const float* predict = (const float*)d_in[0];
    const float* target  = (const float*)d_in[1];
    ncc_main_kernel<<<NBLK, TPB>>>(predict, target, (float*)d_out);
}